// round 1
// baseline (speedup 1.0000x reference)
#include <cuda_runtime.h>
#include <math.h>
#include <stdint.h>

#define NTOK 1024
#define CDIM 768
#define NHEADS 12
#define HD 64
#define GRID_SZ 32
#define ATT_SCALE 0.125f

// ---------------- scratch (device globals; no allocation allowed) ----------------
__device__ float g_h[NTOK * CDIM];        // residual stream
__device__ float g_t[NTOK * CDIM];        // LN out / attn out / neck buffers
__device__ float g_qkv[NTOK * 3 * CDIM];  // qkv
__device__ float g_mid[NTOK * 4 * CDIM];  // mlp hidden / neck conv out

// ---------------- im2col for 16x16 stride-16 patch embed ----------------
__global__ __launch_bounds__(256) void im2col_kernel(const float* __restrict__ x,
                                                     float* __restrict__ out) {
    int idx = blockIdx.x * 256 + threadIdx.x;
    if (idx >= NTOK * CDIM) return;
    int n = idx / CDIM, k = idx % CDIM;
    int gy = n >> 5, gx = n & 31;
    int ph = k / 48;
    int r = k % 48;
    int pw = r / 3, ic = r % 3;
    out[idx] = x[ic * 512 * 512 + (gy * 16 + ph) * 512 + (gx * 16 + pw)];
}

// ---------------- generic SGEMM: C = [res +] act(A @ B + bias) ----------------
// A: MxK row-major, B: KxN row-major. M%64==0, N%64==0, K%16==0 (true for all calls).
template <bool GELU, bool RES>
__global__ __launch_bounds__(256) void gemm_kernel(const float* __restrict__ A,
                                                   const float* __restrict__ B,
                                                   const float* __restrict__ bias,
                                                   const float* __restrict__ res,
                                                   float* __restrict__ C,
                                                   int M, int N, int K) {
    const int BM = 64, BN = 64, BK = 16;
    __shared__ float As[BK][BM];
    __shared__ float Bs[BK][BN];
    int bm = blockIdx.y * BM, bn = blockIdx.x * BN;
    int tid = threadIdx.x;
    int tr = tid / 16, tc = tid % 16;
    float acc[4][4] = {};
    for (int k0 = 0; k0 < K; k0 += BK) {
        #pragma unroll
        for (int i = tid; i < BM * BK; i += 256) {
            int r = i / BK, c = i % BK;
            As[c][r] = A[(size_t)(bm + r) * K + k0 + c];
        }
        #pragma unroll
        for (int i = tid; i < BK * BN; i += 256) {
            int r = i / BN, c = i % BN;
            Bs[r][c] = B[(size_t)(k0 + r) * N + bn + c];
        }
        __syncthreads();
        #pragma unroll
        for (int kk = 0; kk < BK; kk++) {
            float a[4], b[4];
            #pragma unroll
            for (int i = 0; i < 4; i++) a[i] = As[kk][tr * 4 + i];
            #pragma unroll
            for (int j = 0; j < 4; j++) b[j] = Bs[kk][tc * 4 + j];
            #pragma unroll
            for (int i = 0; i < 4; i++)
                #pragma unroll
                for (int j = 0; j < 4; j++) acc[i][j] += a[i] * b[j];
        }
        __syncthreads();
    }
    #pragma unroll
    for (int i = 0; i < 4; i++) {
        int m = bm + tr * 4 + i;
        #pragma unroll
        for (int j = 0; j < 4; j++) {
            int n = bn + tc * 4 + j;
            float v = acc[i][j];
            if (bias) v += bias[n];
            if (GELU) v = 0.5f * v * (1.f + erff(v * 0.70710678118654752f));
            if (RES) v += res[(size_t)m * N + n];
            C[(size_t)m * N + n] = v;
        }
    }
}

// ---------------- LayerNorm over last dim ----------------
__global__ __launch_bounds__(256) void ln_kernel(const float* __restrict__ in,
                                                 const float* __restrict__ w,
                                                 const float* __restrict__ b,
                                                 float* __restrict__ out,
                                                 int C, float eps) {
    int row = blockIdx.x;
    const float* p = in + (size_t)row * C;
    float s = 0.f, ss = 0.f;
    for (int c = threadIdx.x; c < C; c += 256) {
        float v = p[c];
        s += v;
        ss += v * v;
    }
    __shared__ float rs[256], rss[256];
    rs[threadIdx.x] = s;
    rss[threadIdx.x] = ss;
    __syncthreads();
    for (int o = 128; o > 0; o >>= 1) {
        if (threadIdx.x < o) {
            rs[threadIdx.x] += rs[threadIdx.x + o];
            rss[threadIdx.x] += rss[threadIdx.x + o];
        }
        __syncthreads();
    }
    float mean = rs[0] / C;
    float var = rss[0] / C - mean * mean;
    float inv = rsqrtf(var + eps);
    float* q = out + (size_t)row * C;
    for (int c = threadIdx.x; c < C; c += 256)
        q[c] = (p[c] - mean) * inv * w[c] + b[c];
}

// ---------------- global attention: one block per (head, query) ----------------
__global__ __launch_bounds__(256) void attn_global_kernel(const float* __restrict__ qkv,
                                                          const float* __restrict__ rel_h,
                                                          const float* __restrict__ rel_w,
                                                          float* __restrict__ out) {
    int b = blockIdx.x;
    int h = b >> 10;
    int q = b & 1023;
    int qy = q >> 5, qx = q & 31;
    int t = threadIdx.x;
    __shared__ float qs[64];
    __shared__ float ph[32], pw[32];
    __shared__ float logits[1024];
    __shared__ float red[256];
    if (t < 64) qs[t] = qkv[(size_t)q * 2304 + h * 64 + t];
    __syncthreads();
    if (t < 32) {
        const float* r = rel_h + (qy - t + 31) * 64;
        float s = 0.f;
        #pragma unroll
        for (int d = 0; d < 64; d++) s += qs[d] * r[d];
        ph[t] = s;
    } else if (t < 64) {
        int kx = t - 32;
        const float* r = rel_w + (qx - kx + 31) * 64;
        float s = 0.f;
        #pragma unroll
        for (int d = 0; d < 64; d++) s += qs[d] * r[d];
        pw[kx] = s;
    }
    __syncthreads();
    float lmax = -1e30f;
    for (int k = t; k < 1024; k += 256) {
        const float* kv = qkv + (size_t)k * 2304 + 768 + h * 64;
        float s = 0.f;
        #pragma unroll
        for (int d = 0; d < 64; d++) s += qs[d] * kv[d];
        s = s * ATT_SCALE + ph[k >> 5] + pw[k & 31];
        logits[k] = s;
        lmax = fmaxf(lmax, s);
    }
    red[t] = lmax;
    __syncthreads();
    for (int o = 128; o > 0; o >>= 1) {
        if (t < o) red[t] = fmaxf(red[t], red[t + o]);
        __syncthreads();
    }
    float m = red[0];
    __syncthreads();
    float lsum = 0.f;
    for (int k = t; k < 1024; k += 256) {
        float e = __expf(logits[k] - m);
        logits[k] = e;
        lsum += e;
    }
    red[t] = lsum;
    __syncthreads();
    for (int o = 128; o > 0; o >>= 1) {
        if (t < o) red[t] += red[t + o];
        __syncthreads();
    }
    float inv = 1.f / red[0];
    __syncthreads();
    int d = t & 63, sl = t >> 6;
    float acc = 0.f;
    for (int k = sl * 256; k < sl * 256 + 256; k++)
        acc += logits[k] * qkv[(size_t)k * 2304 + 1536 + h * 64 + d];
    red[t] = acc;
    __syncthreads();
    if (t < 64)
        out[(size_t)q * 768 + h * 64 + t] =
            (red[t] + red[t + 64] + red[t + 128] + red[t + 192]) * inv;
}

// ---------------- window attention (14x14 windows, 3x3 grid, padded) ----------------
__global__ __launch_bounds__(256) void attn_window_kernel(const float* __restrict__ qkv,
                                                          const float* __restrict__ rel_h,
                                                          const float* __restrict__ rel_w,
                                                          float* __restrict__ out) {
    int b = blockIdx.x;
    int q = b % 196;
    int wh = b / 196;
    int h = wh % 12;
    int w = wh / 12;
    int wy = w / 3, wx = w % 3;
    int iy = q / 14, ix = q % 14;
    int y = wy * 14 + iy, x = wx * 14 + ix;
    if (y >= 32 || x >= 32) return;  // padded query rows: no output needed
    int qtok = y * 32 + x;
    int t = threadIdx.x;
    __shared__ float qs[64], ph[14], pw[14], logits[196], red[256];
    if (t < 64) qs[t] = qkv[(size_t)qtok * 2304 + h * 64 + t];
    __syncthreads();
    if (t < 14) {
        const float* r = rel_h + (iy - t + 13) * 64;
        float s = 0.f;
        #pragma unroll
        for (int d = 0; d < 64; d++) s += qs[d] * r[d];
        ph[t] = s;
    } else if (t < 28) {
        int kx = t - 14;
        const float* r = rel_w + (ix - kx + 13) * 64;
        float s = 0.f;
        #pragma unroll
        for (int d = 0; d < 64; d++) s += qs[d] * r[d];
        pw[kx] = s;
    }
    __syncthreads();
    if (t < 196) {
        int ky = t / 14, kx = t % 14;
        int yk = wy * 14 + ky, xk = wx * 14 + kx;
        float s = ph[ky] + pw[kx];
        if (yk < 32 && xk < 32) {
            const float* kv = qkv + (size_t)(yk * 32 + xk) * 2304 + 768 + h * 64;
            float dd = 0.f;
            #pragma unroll
            for (int d = 0; d < 64; d++) dd += qs[d] * kv[d];
            s += dd * ATT_SCALE;
        }
        logits[t] = s;
    }
    red[t] = (t < 196) ? logits[t] : -1e30f;
    __syncthreads();
    for (int o = 128; o > 0; o >>= 1) {
        if (t < o) red[t] = fmaxf(red[t], red[t + o]);
        __syncthreads();
    }
    float m = red[0];
    __syncthreads();
    float e = 0.f;
    if (t < 196) {
        e = __expf(logits[t] - m);
        logits[t] = e;
    }
    red[t] = e;
    __syncthreads();
    for (int o = 128; o > 0; o >>= 1) {
        if (t < o) red[t] += red[t + o];
        __syncthreads();
    }
    float inv = 1.f / red[0];
    __syncthreads();
    int d = t & 63, sl = t >> 6;  // 196 = 4 * 49
    float acc = 0.f;
    for (int k = sl * 49; k < sl * 49 + 49; k++) {
        int ky = k / 14, kx = k % 14;
        int yk = wy * 14 + ky, xk = wx * 14 + kx;
        if (yk < 32 && xk < 32)
            acc += logits[k] * qkv[(size_t)(yk * 32 + xk) * 2304 + 1536 + h * 64 + d];
    }
    red[t] = acc;
    __syncthreads();
    if (t < 64)
        out[(size_t)qtok * 768 + h * 64 + t] =
            (red[t] + red[t + 64] + red[t + 128] + red[t + 192]) * inv;
}

// ---------------- 3x3 conv, 256->256, SAME, on 32x32 spatial ----------------
__global__ __launch_bounds__(256) void conv3_kernel(const float* __restrict__ in,
                                                    const float* __restrict__ w,
                                                    float* __restrict__ out) {
    int n = blockIdx.x;
    int y = n / 32, x = n % 32;
    int co = threadIdx.x;
    __shared__ float s_in[9 * 256];
    #pragma unroll
    for (int p = 0; p < 9; p++) {
        int dy = p / 3 - 1, dx = p % 3 - 1;
        int yy = y + dy, xx = x + dx;
        s_in[p * 256 + co] =
            (yy >= 0 && yy < 32 && xx >= 0 && xx < 32) ? in[(size_t)(yy * 32 + xx) * 256 + co] : 0.f;
    }
    __syncthreads();
    float acc = 0.f;
    for (int p = 0; p < 9; p++) {
        const float* wp = w + (size_t)p * 256 * 256 + co;
        const float* ip = s_in + p * 256;
        #pragma unroll 8
        for (int ci = 0; ci < 256; ci++) acc += ip[ci] * wp[(size_t)ci * 256];
    }
    out[(size_t)n * 256 + co] = acc;
}

// ---------------- NHWC(1024,256) -> NCHW(256,1024) transpose ----------------
__global__ __launch_bounds__(256) void transpose_out_kernel(const float* __restrict__ in,
                                                            float* __restrict__ out) {
    int idx = blockIdx.x * 256 + threadIdx.x;
    if (idx >= 256 * 1024) return;
    int c = idx / 1024;
    int n = idx % 1024;
    out[idx] = in[(size_t)n * 256 + c];
}

// ---------------- orchestration ----------------
extern "C" void kernel_launch(void* const* d_in, const int* in_sizes, int n_in,
                              void* d_out, int out_size) {
    const float* x          = (const float*)d_in[0];
    const float* patch_w    = (const float*)d_in[1];
    const float* patch_b    = (const float*)d_in[2];
    const float* pos_embed  = (const float*)d_in[3];
    const float* ln1_w      = (const float*)d_in[4];
    const float* ln1_b      = (const float*)d_in[5];
    const float* qkv_w      = (const float*)d_in[6];
    const float* qkv_b      = (const float*)d_in[7];
    const float* proj_w     = (const float*)d_in[8];
    const float* proj_b     = (const float*)d_in[9];
    const float* ln2_w      = (const float*)d_in[10];
    const float* ln2_b      = (const float*)d_in[11];
    const float* fc1_w      = (const float*)d_in[12];
    const float* fc1_b      = (const float*)d_in[13];
    const float* fc2_w      = (const float*)d_in[14];
    const float* fc2_b      = (const float*)d_in[15];
    const float* rel_h_win  = (const float*)d_in[16];
    const float* rel_w_win  = (const float*)d_in[17];
    const float* rel_h_glob = (const float*)d_in[18];
    const float* rel_w_glob = (const float*)d_in[19];
    const float* neck_w1    = (const float*)d_in[20];
    const float* neck_ln1_w = (const float*)d_in[21];
    const float* neck_ln1_b = (const float*)d_in[22];
    const float* neck_w2    = (const float*)d_in[23];
    const float* neck_ln2_w = (const float*)d_in[24];
    const float* neck_ln2_b = (const float*)d_in[25];

    float *h, *t, *qkv, *mid;
    cudaGetSymbolAddress((void**)&h, g_h);
    cudaGetSymbolAddress((void**)&t, g_t);
    cudaGetSymbolAddress((void**)&qkv, g_qkv);
    cudaGetSymbolAddress((void**)&mid, g_mid);

    // patch embed: im2col + GEMM(+bias) + pos_embed (as residual)
    im2col_kernel<<<(NTOK * CDIM + 255) / 256, 256>>>(x, t);
    gemm_kernel<false, true><<<dim3(768 / 64, NTOK / 64), 256>>>(
        t, patch_w, patch_b, pos_embed, h, NTOK, 768, 768);

    int wi = 0, gi = 0;
    for (int i = 0; i < 12; i++) {
        bool is_glob = (i == 2 || i == 5 || i == 8 || i == 11);
        ln_kernel<<<NTOK, 256>>>(h, ln1_w + i * 768, ln1_b + i * 768, t, 768, 1e-5f);
        gemm_kernel<false, false><<<dim3(2304 / 64, NTOK / 64), 256>>>(
            t, qkv_w + (size_t)i * 768 * 2304, qkv_b + (size_t)i * 2304, nullptr, qkv,
            NTOK, 2304, 768);
        if (is_glob) {
            attn_global_kernel<<<12 * 1024, 256>>>(
                qkv, rel_h_glob + (size_t)gi * 63 * 64, rel_w_glob + (size_t)gi * 63 * 64, t);
            gi++;
        } else {
            attn_window_kernel<<<9 * 12 * 196, 256>>>(
                qkv, rel_h_win + (size_t)wi * 27 * 64, rel_w_win + (size_t)wi * 27 * 64, t);
            wi++;
        }
        gemm_kernel<false, true><<<dim3(768 / 64, NTOK / 64), 256>>>(
            t, proj_w + (size_t)i * 768 * 768, proj_b + (size_t)i * 768, h, h,
            NTOK, 768, 768);
        ln_kernel<<<NTOK, 256>>>(h, ln2_w + i * 768, ln2_b + i * 768, t, 768, 1e-5f);
        gemm_kernel<true, false><<<dim3(3072 / 64, NTOK / 64), 256>>>(
            t, fc1_w + (size_t)i * 768 * 3072, fc1_b + (size_t)i * 3072, nullptr, mid,
            NTOK, 3072, 768);
        gemm_kernel<false, true><<<dim3(768 / 64, NTOK / 64), 256>>>(
            mid, fc2_w + (size_t)i * 3072 * 768, fc2_b + (size_t)i * 768, h, h,
            NTOK, 768, 3072);
    }

    // neck
    gemm_kernel<false, false><<<dim3(256 / 64, NTOK / 64), 256>>>(
        h, neck_w1, nullptr, nullptr, t, NTOK, 256, 768);
    ln_kernel<<<NTOK, 256>>>(t, neck_ln1_w, neck_ln1_b, t, 256, 1e-6f);
    conv3_kernel<<<NTOK, 256>>>(t, neck_w2, mid);
    ln_kernel<<<NTOK, 256>>>(mid, neck_ln2_w, neck_ln2_b, mid, 256, 1e-6f);
    transpose_out_kernel<<<(256 * 1024 + 255) / 256, 256>>>(mid, (float*)d_out);
}

// round 3
// speedup vs baseline: 3.7142x; 3.7142x over previous
#include <cuda_runtime.h>
#include <math.h>
#include <stdint.h>

#define NTOK 1024
#define CDIM 768
#define ATT_SCALE 0.125f

// ---------------- scratch (device globals; no allocation allowed) ----------------
__device__ float g_h[NTOK * CDIM];
__device__ float g_t[NTOK * CDIM];
__device__ float g_qkv[NTOK * 3 * CDIM];
__device__ float g_mid[NTOK * 4 * CDIM];
// attention scratch: max(global: 12*1024*64, window: 108*256*64) = 1769472 floats each
#define ATT_BUF 1769472
__device__ float g_Q[ATT_BUF];
__device__ float g_Kt[ATT_BUF];
__device__ float g_V[ATT_BUF];
__device__ float g_O[ATT_BUF];
// S scores: max(12*1024*1024, 108*256*256) = 12582912 floats
__device__ float g_S[12 * 1024 * 1024];

// ---------------- tf32 helper ----------------
__device__ __forceinline__ uint32_t f2tf(float f) {
    uint32_t u;
    asm("cvt.rna.tf32.f32 %0, %1;" : "=r"(u) : "f"(f));
    return u;
}

// ---------------- tf32 tensor-core GEMM ----------------
// C[b] = [res +] act(A[b] @ B[b] + bias).  A: MxK row-major, B: KxN row-major.
// M%64==0, N%64==0, K%16==0.  128 threads, 64x64 tile, warp tile 32x32.
template <bool GELU, bool RES>
__global__ __launch_bounds__(128) void gemm_tc(const float* __restrict__ A,
                                               const float* __restrict__ B,
                                               const float* __restrict__ bias,
                                               const float* __restrict__ res,
                                               float* __restrict__ C,
                                               int M, int N, int K,
                                               long sA, long sB, long sC) {
    A += (long)blockIdx.z * sA;
    B += (long)blockIdx.z * sB;
    C += (long)blockIdx.z * sC;
    __shared__ uint32_t As[16][68];
    __shared__ uint32_t Bs[16][68];
    int bm = blockIdx.y * 64, bn = blockIdx.x * 64;
    int tid = threadIdx.x;
    int lane = tid & 31, w = tid >> 5;
    int wm = (w & 1) * 32, wn = (w >> 1) * 32;
    int g = lane >> 2, tig = lane & 3;
    float acc[2][4][4];
    #pragma unroll
    for (int i = 0; i < 2; i++)
        #pragma unroll
        for (int j = 0; j < 4; j++)
            #pragma unroll
            for (int l = 0; l < 4; l++) acc[i][j][l] = 0.f;

    for (int k0 = 0; k0 < K; k0 += 16) {
        // load A tile (64 rows x 16), store transposed As[k][m]
        #pragma unroll
        for (int i = 0; i < 2; i++) {
            int it = tid + i * 128;
            int r = it >> 2, c4 = (it & 3) * 4;
            float4 a4 = *(const float4*)(A + (size_t)(bm + r) * K + k0 + c4);
            As[c4 + 0][r] = f2tf(a4.x);
            As[c4 + 1][r] = f2tf(a4.y);
            As[c4 + 2][r] = f2tf(a4.z);
            As[c4 + 3][r] = f2tf(a4.w);
        }
        // load B tile (16 rows x 64) into Bs[k][n]
        #pragma unroll
        for (int i = 0; i < 2; i++) {
            int it = tid + i * 128;
            int r = it >> 4, c4 = (it & 15) * 4;
            float4 b4 = *(const float4*)(B + (size_t)(k0 + r) * N + bn + c4);
            Bs[r][c4 + 0] = f2tf(b4.x);
            Bs[r][c4 + 1] = f2tf(b4.y);
            Bs[r][c4 + 2] = f2tf(b4.z);
            Bs[r][c4 + 3] = f2tf(b4.w);
        }
        __syncthreads();
        #pragma unroll
        for (int ks = 0; ks < 16; ks += 8) {
            uint32_t af[2][4], bf[4][2];
            #pragma unroll
            for (int mf = 0; mf < 2; mf++) {
                int mbase = wm + mf * 16 + g;
                af[mf][0] = As[ks + tig][mbase];
                af[mf][1] = As[ks + tig][mbase + 8];
                af[mf][2] = As[ks + tig + 4][mbase];
                af[mf][3] = As[ks + tig + 4][mbase + 8];
            }
            #pragma unroll
            for (int nf = 0; nf < 4; nf++) {
                int nbase = wn + nf * 8 + g;
                bf[nf][0] = Bs[ks + tig][nbase];
                bf[nf][1] = Bs[ks + tig + 4][nbase];
            }
            #pragma unroll
            for (int mf = 0; mf < 2; mf++)
                #pragma unroll
                for (int nf = 0; nf < 4; nf++) {
                    asm volatile(
                        "mma.sync.aligned.m16n8k8.row.col.f32.tf32.tf32.f32 "
                        "{%0,%1,%2,%3}, {%4,%5,%6,%7}, {%8,%9}, {%0,%1,%2,%3};"
                        : "+f"(acc[mf][nf][0]), "+f"(acc[mf][nf][1]),
                          "+f"(acc[mf][nf][2]), "+f"(acc[mf][nf][3])
                        : "r"(af[mf][0]), "r"(af[mf][1]), "r"(af[mf][2]), "r"(af[mf][3]),
                          "r"(bf[nf][0]), "r"(bf[nf][1]));
                }
        }
        __syncthreads();
    }
    // epilogue
    #pragma unroll
    for (int mf = 0; mf < 2; mf++) {
        #pragma unroll
        for (int nf = 0; nf < 4; nf++) {
            int row0 = bm + wm + mf * 16 + g;
            int col0 = bn + wn + nf * 8 + tig * 2;
            #pragma unroll
            for (int e = 0; e < 4; e++) {
                int m = row0 + (e >> 1) * 8;
                int n = col0 + (e & 1);
                float v = acc[mf][nf][e];
                if (bias) v += bias[n];
                if (GELU) v = 0.5f * v * (1.f + erff(v * 0.70710678118654752f));
                if (RES) v += res[(size_t)m * N + n];
                C[(size_t)m * N + n] = v;
            }
        }
    }
}

// ---------------- im2col for 16x16 stride-16 patch embed ----------------
__global__ __launch_bounds__(256) void im2col_kernel(const float* __restrict__ x,
                                                     float* __restrict__ out) {
    int idx = blockIdx.x * 256 + threadIdx.x;
    if (idx >= NTOK * CDIM) return;
    int n = idx / CDIM, k = idx % CDIM;
    int gy = n >> 5, gx = n & 31;
    int ph = k / 48;
    int r = k % 48;
    int pw = r / 3, ic = r % 3;
    out[idx] = x[ic * 512 * 512 + (gy * 16 + ph) * 512 + (gx * 16 + pw)];
}

// ---------------- LayerNorm over last dim ----------------
__global__ __launch_bounds__(256) void ln_kernel(const float* __restrict__ in,
                                                 const float* __restrict__ w,
                                                 const float* __restrict__ b,
                                                 float* __restrict__ out,
                                                 int C, float eps) {
    int row = blockIdx.x;
    const float* p = in + (size_t)row * C;
    float s = 0.f, ss = 0.f;
    for (int c = threadIdx.x; c < C; c += 256) {
        float v = p[c];
        s += v;
        ss += v * v;
    }
    __shared__ float rs[256], rss[256];
    rs[threadIdx.x] = s;
    rss[threadIdx.x] = ss;
    __syncthreads();
    for (int o = 128; o > 0; o >>= 1) {
        if (threadIdx.x < o) {
            rs[threadIdx.x] += rs[threadIdx.x + o];
            rss[threadIdx.x] += rss[threadIdx.x + o];
        }
        __syncthreads();
    }
    float mean = rs[0] / C;
    float var = rss[0] / C - mean * mean;
    float inv = rsqrtf(var + eps);
    float* q = out + (size_t)row * C;
    for (int c = threadIdx.x; c < C; c += 256)
        q[c] = (p[c] - mean) * inv * w[c] + b[c];
}

// ---------------- qkv repack: global ----------------
// Q[h][n][d], Kt[h][d][n], V[h][n][d]
__global__ __launch_bounds__(256) void repack_glob(const float* __restrict__ qkv,
                                                   float* __restrict__ Q,
                                                   float* __restrict__ Kt,
                                                   float* __restrict__ V) {
    int idx = blockIdx.x * 256 + threadIdx.x;  // 12*1024*64
    int h = idx >> 16;
    int n = (idx >> 6) & 1023;
    int d = idx & 63;
    size_t base = (size_t)n * 2304 + h * 64 + d;
    Q[idx] = qkv[base];
    Kt[((size_t)h * 64 + d) * 1024 + n] = qkv[base + 768];
    V[idx] = qkv[base + 1536];
}

// ---------------- qkv repack: window (pad each 14x14=196 window to 256 rows) ----------------
__global__ __launch_bounds__(256) void repack_win(const float* __restrict__ qkv,
                                                  float* __restrict__ Q,
                                                  float* __restrict__ Kt,
                                                  float* __restrict__ V) {
    int idx = blockIdx.x * 256 + threadIdx.x;  // 108*256*64
    int bh = idx >> 14;       // window*12+head
    int r = (idx >> 6) & 255; // row within padded 256
    int d = idx & 63;
    int w = bh / 12, h = bh % 12;
    int wy = w / 3, wx = w % 3;
    float q = 0.f, k = 0.f, v = 0.f;
    if (r < 196) {
        int iy = r / 14, ix = r % 14;
        int y = wy * 14 + iy, x = wx * 14 + ix;
        if (y < 32 && x < 32) {
            size_t base = (size_t)(y * 32 + x) * 2304 + h * 64 + d;
            q = qkv[base];
            k = qkv[base + 768];
            v = qkv[base + 1536];
        }
    }
    Q[idx] = q;
    Kt[((size_t)bh * 64 + d) * 256 + r] = k;
    V[idx] = v;
}

// ---------------- softmax + rel-pos: global (row = 1024 keys) ----------------
__global__ __launch_bounds__(256) void softmax_glob(float* __restrict__ S,
                                                    const float* __restrict__ Q,
                                                    const float* __restrict__ rel_h,
                                                    const float* __restrict__ rel_w) {
    int b = blockIdx.x;
    int h = b >> 10, q = b & 1023;
    int qy = q >> 5, qx = q & 31;
    int t = threadIdx.x;
    __shared__ float qs[64], ph[32], pw[32], row[1024], red[256];
    float* Srow = S + ((size_t)h * 1024 + q) * 1024;
    if (t < 64) qs[t] = Q[((size_t)h * 1024 + q) * 64 + t];
    __syncthreads();
    if (t < 32) {
        const float* r = rel_h + (qy - t + 31) * 64;
        float s = 0.f;
        #pragma unroll
        for (int d = 0; d < 64; d++) s += qs[d] * r[d];
        ph[t] = s;
    } else if (t < 64) {
        int kx = t - 32;
        const float* r = rel_w + (qx - kx + 31) * 64;
        float s = 0.f;
        #pragma unroll
        for (int d = 0; d < 64; d++) s += qs[d] * r[d];
        pw[kx] = s;
    }
    __syncthreads();
    float lmax = -1e30f;
    for (int k = t; k < 1024; k += 256) {
        float s = Srow[k] * ATT_SCALE + ph[k >> 5] + pw[k & 31];
        row[k] = s;
        lmax = fmaxf(lmax, s);
    }
    red[t] = lmax;
    __syncthreads();
    for (int o = 128; o > 0; o >>= 1) {
        if (t < o) red[t] = fmaxf(red[t], red[t + o]);
        __syncthreads();
    }
    float m = red[0];
    __syncthreads();
    float lsum = 0.f;
    for (int k = t; k < 1024; k += 256) {
        float e = __expf(row[k] - m);
        row[k] = e;
        lsum += e;
    }
    red[t] = lsum;
    __syncthreads();
    for (int o = 128; o > 0; o >>= 1) {
        if (t < o) red[t] += red[t + o];
        __syncthreads();
    }
    float inv = 1.f / red[0];
    __syncthreads();
    for (int k = t; k < 1024; k += 256) Srow[k] = row[k] * inv;
}

// ---------------- softmax + rel-pos: window (256 padded keys, 196 real) ----------------
__global__ __launch_bounds__(256) void softmax_win(float* __restrict__ S,
                                                   const float* __restrict__ Q,
                                                   const float* __restrict__ rel_h,
                                                   const float* __restrict__ rel_w) {
    int b = blockIdx.x;
    int bh = b >> 8, r = b & 255;
    int t = threadIdx.x;
    float* Srow = S + ((size_t)bh * 256 + r) * 256;
    if (r >= 196) {
        Srow[t] = 0.f;
        return;
    }
    int iy = r / 14, ix = r % 14;
    __shared__ float qs[64], ph[14], pw[14], red[256];
    if (t < 64) qs[t] = Q[((size_t)bh * 256 + r) * 64 + t];
    __syncthreads();
    if (t < 14) {
        const float* rp = rel_h + (iy - t + 13) * 64;
        float s = 0.f;
        #pragma unroll
        for (int d = 0; d < 64; d++) s += qs[d] * rp[d];
        ph[t] = s;
    } else if (t < 28) {
        int kx = t - 14;
        const float* rp = rel_w + (ix - kx + 13) * 64;
        float s = 0.f;
        #pragma unroll
        for (int d = 0; d < 64; d++) s += qs[d] * rp[d];
        pw[kx] = s;
    }
    __syncthreads();
    float s = -1e30f;
    if (t < 196) s = Srow[t] * ATT_SCALE + ph[t / 14] + pw[t % 14];
    red[t] = s;
    __syncthreads();
    for (int o = 128; o > 0; o >>= 1) {
        if (t < o) red[t] = fmaxf(red[t], red[t + o]);
        __syncthreads();
    }
    float m = red[0];
    __syncthreads();
    float e = (t < 196) ? __expf(s - m) : 0.f;
    red[t] = e;
    __syncthreads();
    for (int o = 128; o > 0; o >>= 1) {
        if (t < o) red[t] += red[t + o];
        __syncthreads();
    }
    Srow[t] = e / red[0];
}

// ---------------- attention out repack back to token-major ----------------
__global__ __launch_bounds__(256) void repack_back_glob(const float* __restrict__ O,
                                                        float* __restrict__ out) {
    int idx = blockIdx.x * 256 + threadIdx.x;  // 1024*768
    int n = idx / 768, c = idx % 768;
    int h = c >> 6, d = c & 63;
    out[idx] = O[((size_t)h * 1024 + n) * 64 + d];
}

__global__ __launch_bounds__(256) void repack_back_win(const float* __restrict__ O,
                                                       float* __restrict__ out) {
    int idx = blockIdx.x * 256 + threadIdx.x;  // 1024*768
    int n = idx / 768, c = idx % 768;
    int h = c >> 6, d = c & 63;
    int y = n >> 5, x = n & 31;
    int w = (y / 14) * 3 + (x / 14);
    int r = (y % 14) * 14 + (x % 14);
    out[idx] = O[(((size_t)(w * 12 + h)) * 256 + r) * 64 + d];
}

// ---------------- 3x3 conv, 256->256, SAME, 32x32 spatial ----------------
__global__ __launch_bounds__(256) void conv3_kernel(const float* __restrict__ in,
                                                    const float* __restrict__ w,
                                                    float* __restrict__ out) {
    int n = blockIdx.x;
    int y = n / 32, x = n % 32;
    int co = threadIdx.x;
    __shared__ float s_in[9 * 256];
    #pragma unroll
    for (int p = 0; p < 9; p++) {
        int dy = p / 3 - 1, dx = p % 3 - 1;
        int yy = y + dy, xx = x + dx;
        s_in[p * 256 + co] =
            (yy >= 0 && yy < 32 && xx >= 0 && xx < 32) ? in[(size_t)(yy * 32 + xx) * 256 + co] : 0.f;
    }
    __syncthreads();
    float acc = 0.f;
    for (int p = 0; p < 9; p++) {
        const float* wp = w + (size_t)p * 256 * 256 + co;
        const float* ip = s_in + p * 256;
        #pragma unroll 8
        for (int ci = 0; ci < 256; ci++) acc += ip[ci] * wp[(size_t)ci * 256];
    }
    out[(size_t)n * 256 + co] = acc;
}

// ---------------- NHWC(1024,256) -> NCHW(256,1024) ----------------
__global__ __launch_bounds__(256) void transpose_out_kernel(const float* __restrict__ in,
                                                            float* __restrict__ out) {
    int idx = blockIdx.x * 256 + threadIdx.x;
    if (idx >= 256 * 1024) return;
    int c = idx / 1024;
    int n = idx % 1024;
    out[idx] = in[(size_t)n * 256 + c];
}

// ---------------- orchestration ----------------
extern "C" void kernel_launch(void* const* d_in, const int* in_sizes, int n_in,
                              void* d_out, int out_size) {
    const float* x          = (const float*)d_in[0];
    const float* patch_w    = (const float*)d_in[1];
    const float* patch_b    = (const float*)d_in[2];
    const float* pos_embed  = (const float*)d_in[3];
    const float* ln1_w      = (const float*)d_in[4];
    const float* ln1_b      = (const float*)d_in[5];
    const float* qkv_w      = (const float*)d_in[6];
    const float* qkv_b      = (const float*)d_in[7];
    const float* proj_w     = (const float*)d_in[8];
    const float* proj_b     = (const float*)d_in[9];
    const float* ln2_w      = (const float*)d_in[10];
    const float* ln2_b      = (const float*)d_in[11];
    const float* fc1_w      = (const float*)d_in[12];
    const float* fc1_b      = (const float*)d_in[13];
    const float* fc2_w      = (const float*)d_in[14];
    const float* fc2_b      = (const float*)d_in[15];
    const float* rel_h_win  = (const float*)d_in[16];
    const float* rel_w_win  = (const float*)d_in[17];
    const float* rel_h_glob = (const float*)d_in[18];
    const float* rel_w_glob = (const float*)d_in[19];
    const float* neck_w1    = (const float*)d_in[20];
    const float* neck_ln1_w = (const float*)d_in[21];
    const float* neck_ln1_b = (const float*)d_in[22];
    const float* neck_w2    = (const float*)d_in[23];
    const float* neck_ln2_w = (const float*)d_in[24];
    const float* neck_ln2_b = (const float*)d_in[25];

    float *h, *t, *qkv, *mid, *Q, *Kt, *V, *O, *S;
    cudaGetSymbolAddress((void**)&h, g_h);
    cudaGetSymbolAddress((void**)&t, g_t);
    cudaGetSymbolAddress((void**)&qkv, g_qkv);
    cudaGetSymbolAddress((void**)&mid, g_mid);
    cudaGetSymbolAddress((void**)&Q, g_Q);
    cudaGetSymbolAddress((void**)&Kt, g_Kt);
    cudaGetSymbolAddress((void**)&V, g_V);
    cudaGetSymbolAddress((void**)&O, g_O);
    cudaGetSymbolAddress((void**)&S, g_S);

    // patch embed: im2col + GEMM(+bias) + pos_embed residual
    im2col_kernel<<<(NTOK * CDIM + 255) / 256, 256>>>(x, t);
    gemm_tc<false, true><<<dim3(768 / 64, NTOK / 64, 1), 128>>>(
        t, patch_w, patch_b, pos_embed, h, NTOK, 768, 768, 0, 0, 0);

    int wi = 0, gi = 0;
    for (int i = 0; i < 12; i++) {
        bool is_glob = (i == 2 || i == 5 || i == 8 || i == 11);
        ln_kernel<<<NTOK, 256>>>(h, ln1_w + i * 768, ln1_b + i * 768, t, 768, 1e-5f);
        gemm_tc<false, false><<<dim3(2304 / 64, NTOK / 64, 1), 128>>>(
            t, qkv_w + (size_t)i * 768 * 2304, qkv_b + (size_t)i * 2304, nullptr, qkv,
            NTOK, 2304, 768, 0, 0, 0);
        if (is_glob) {
            repack_glob<<<12 * 1024 * 64 / 256, 256>>>(qkv, Q, Kt, V);
            // S[h] = Q[h] (1024x64) @ Kt[h] (64x1024)
            gemm_tc<false, false><<<dim3(16, 16, 12), 128>>>(
                Q, Kt, nullptr, nullptr, S, 1024, 1024, 64,
                1024L * 64, 64L * 1024, 1024L * 1024);
            softmax_glob<<<12 * 1024, 256>>>(
                S, Q, rel_h_glob + (size_t)gi * 63 * 64, rel_w_glob + (size_t)gi * 63 * 64);
            // O[h] = P[h] (1024x1024) @ V[h] (1024x64)
            gemm_tc<false, false><<<dim3(1, 16, 12), 128>>>(
                S, V, nullptr, nullptr, O, 1024, 64, 1024,
                1024L * 1024, 1024L * 64, 1024L * 64);
            repack_back_glob<<<NTOK * 768 / 256, 256>>>(O, t);
            gi++;
        } else {
            repack_win<<<108 * 256 * 64 / 256, 256>>>(qkv, Q, Kt, V);
            // S[wh] = Q[wh] (256x64) @ Kt[wh] (64x256)
            gemm_tc<false, false><<<dim3(4, 4, 108), 128>>>(
                Q, Kt, nullptr, nullptr, S, 256, 256, 64,
                256L * 64, 64L * 256, 256L * 256);
            softmax_win<<<108 * 256, 256>>>(
                S, Q, rel_h_win + (size_t)wi * 27 * 64, rel_w_win + (size_t)wi * 27 * 64);
            // O[wh] = P[wh] (256x256) @ V[wh] (256x64)
            gemm_tc<false, false><<<dim3(1, 4, 108), 128>>>(
                S, V, nullptr, nullptr, O, 256, 64, 256,
                256L * 256, 256L * 64, 256L * 64);
            repack_back_win<<<NTOK * 768 / 256, 256>>>(O, t);
            wi++;
        }
        gemm_tc<false, true><<<dim3(768 / 64, NTOK / 64, 1), 128>>>(
            t, proj_w + (size_t)i * 768 * 768, proj_b + (size_t)i * 768, h, h,
            NTOK, 768, 768, 0, 0, 0);
        ln_kernel<<<NTOK, 256>>>(h, ln2_w + i * 768, ln2_b + i * 768, t, 768, 1e-5f);
        gemm_tc<true, false><<<dim3(3072 / 64, NTOK / 64, 1), 128>>>(
            t, fc1_w + (size_t)i * 768 * 3072, fc1_b + (size_t)i * 3072, nullptr, mid,
            NTOK, 3072, 768, 0, 0, 0);
        gemm_tc<false, true><<<dim3(768 / 64, NTOK / 64, 1), 128>>>(
            mid, fc2_w + (size_t)i * 3072 * 768, fc2_b + (size_t)i * 768, h, h,
            NTOK, 768, 3072, 0, 0, 0);
    }

    // neck
    gemm_tc<false, false><<<dim3(256 / 64, NTOK / 64, 1), 128>>>(
        h, neck_w1, nullptr, nullptr, t, NTOK, 256, 768, 0, 0, 0);
    ln_kernel<<<NTOK, 256>>>(t, neck_ln1_w, neck_ln1_b, t, 256, 1e-6f);
    conv3_kernel<<<NTOK, 256>>>(t, neck_w2, mid);
    ln_kernel<<<NTOK, 256>>>(mid, neck_ln2_w, neck_ln2_b, mid, 256, 1e-6f);
    transpose_out_kernel<<<(256 * 1024 + 255) / 256, 256>>>(mid, (float*)d_out);
}

// round 8
// speedup vs baseline: 3.7182x; 1.0011x over previous
#include <cuda_runtime.h>
#include <math.h>
#include <stdint.h>

#define NTOK 1024
#define CDIM 768
#define ATT_SCALE 0.125f

// ---------------- scratch (device globals; no allocation allowed) ----------------
__device__ float g_h[NTOK * CDIM];
__device__ float g_t[NTOK * CDIM];
__device__ float g_qkv[NTOK * 3 * CDIM];
__device__ float g_mid[NTOK * 4 * CDIM];
#define ATT_BUF 1769472
__device__ float g_Q[ATT_BUF];
__device__ float g_Kt[ATT_BUF];   // window K, token-major
__device__ float g_V[ATT_BUF];
__device__ float g_O[ATT_BUF];
__device__ float g_S[12 * 1024 * 1024];

// ---------------- tf32 helper ----------------
__device__ __forceinline__ uint32_t f2tf(float f) {
    uint32_t u;
    asm("cvt.rna.tf32.f32 %0, %1;" : "=r"(u) : "f"(f));
    return u;
}

// ---------------- tf32 tensor-core GEMM, 128x{128|64} block tile, 4 warps ----------------
// C = [res +] act(A @ B + bias).  A: MxK row-major (ldA).
// B: if !TRB, KxN row-major (ldB); if TRB, B is NxK row-major (ldB) and we compute A @ B^T.
// M%128==0, N%BN==0, K%16==0.
template <int BN, bool TRB, bool GELU, bool RES>
__global__ __launch_bounds__(128) void gemm_tc(const float* __restrict__ A,
                                               const float* __restrict__ B,
                                               const float* __restrict__ bias,
                                               const float* __restrict__ res,
                                               float* __restrict__ C,
                                               int M, int N, int K,
                                               int ldA, int ldB, int ldC,
                                               long sA, long sB, long sC) {
    constexpr int NF = BN / 16;  // 8-wide n-frags per warp
    A += (long)blockIdx.z * sA;
    B += (long)blockIdx.z * sB;
    C += (long)blockIdx.z * sC;
    if (RES) res += (long)blockIdx.z * sC;

    __shared__ uint32_t As[16][132];
    __shared__ uint32_t Bs[16][BN + 4];

    int bm = blockIdx.y * 128, bn = blockIdx.x * BN;
    int tid = threadIdx.x;
    int lane = tid & 31, w = tid >> 5;
    int wm = (w & 1) * 64, wn = (w >> 1) * (BN / 2);
    int g = lane >> 2, tig = lane & 3;

    float acc[4][NF][4];
    #pragma unroll
    for (int i = 0; i < 4; i++)
        #pragma unroll
        for (int j = 0; j < NF; j++)
            #pragma unroll
            for (int l = 0; l < 4; l++) acc[i][j][l] = 0.f;

    for (int k0 = 0; k0 < K; k0 += 16) {
        // A tile: 128 rows x 16 cols -> As[k][m] (transposed store)
        #pragma unroll
        for (int i = 0; i < 4; i++) {
            int it = tid + i * 128;
            int r = it >> 2, c4 = (it & 3) * 4;
            float4 a4 = *(const float4*)(A + (size_t)(bm + r) * ldA + k0 + c4);
            As[c4 + 0][r] = f2tf(a4.x);
            As[c4 + 1][r] = f2tf(a4.y);
            As[c4 + 2][r] = f2tf(a4.z);
            As[c4 + 3][r] = f2tf(a4.w);
        }
        // B tile -> Bs[k][n]
        if (TRB) {
            #pragma unroll
            for (int i = 0; i < BN / 32; i++) {
                int it = tid + i * 128;
                int r = it >> 2, c4 = (it & 3) * 4;
                float4 b4 = *(const float4*)(B + (size_t)(bn + r) * ldB + k0 + c4);
                Bs[c4 + 0][r] = f2tf(b4.x);
                Bs[c4 + 1][r] = f2tf(b4.y);
                Bs[c4 + 2][r] = f2tf(b4.z);
                Bs[c4 + 3][r] = f2tf(b4.w);
            }
        } else {
            constexpr int FPR = BN / 4;  // float4 per B row
            #pragma unroll
            for (int i = 0; i < BN / 32; i++) {
                int it = tid + i * 128;
                int r = it / FPR, c4 = (it % FPR) * 4;
                float4 b4 = *(const float4*)(B + (size_t)(k0 + r) * ldB + bn + c4);
                Bs[r][c4 + 0] = f2tf(b4.x);
                Bs[r][c4 + 1] = f2tf(b4.y);
                Bs[r][c4 + 2] = f2tf(b4.z);
                Bs[r][c4 + 3] = f2tf(b4.w);
            }
        }
        __syncthreads();
        #pragma unroll
        for (int ks = 0; ks < 16; ks += 8) {
            uint32_t af[4][4], bf[NF][2];
            #pragma unroll
            for (int mf = 0; mf < 4; mf++) {
                int mbase = wm + mf * 16 + g;
                af[mf][0] = As[ks + tig][mbase];
                af[mf][1] = As[ks + tig][mbase + 8];
                af[mf][2] = As[ks + tig + 4][mbase];
                af[mf][3] = As[ks + tig + 4][mbase + 8];
            }
            #pragma unroll
            for (int nf = 0; nf < NF; nf++) {
                int nbase = wn + nf * 8 + g;
                bf[nf][0] = Bs[ks + tig][nbase];
                bf[nf][1] = Bs[ks + tig + 4][nbase];
            }
            #pragma unroll
            for (int mf = 0; mf < 4; mf++)
                #pragma unroll
                for (int nf = 0; nf < NF; nf++) {
                    asm volatile(
                        "mma.sync.aligned.m16n8k8.row.col.f32.tf32.tf32.f32 "
                        "{%0,%1,%2,%3}, {%4,%5,%6,%7}, {%8,%9}, {%0,%1,%2,%3};"
                        : "+f"(acc[mf][nf][0]), "+f"(acc[mf][nf][1]),
                          "+f"(acc[mf][nf][2]), "+f"(acc[mf][nf][3])
                        : "r"(af[mf][0]), "r"(af[mf][1]), "r"(af[mf][2]), "r"(af[mf][3]),
                          "r"(bf[nf][0]), "r"(bf[nf][1]));
                }
        }
        __syncthreads();
    }
    // epilogue
    #pragma unroll
    for (int mf = 0; mf < 4; mf++) {
        #pragma unroll
        for (int nf = 0; nf < NF; nf++) {
            int row0 = bm + wm + mf * 16 + g;
            int col0 = bn + wn + nf * 8 + tig * 2;
            #pragma unroll
            for (int e = 0; e < 4; e++) {
                int m = row0 + (e >> 1) * 8;
                int n = col0 + (e & 1);
                float v = acc[mf][nf][e];
                if (bias) v += bias[n];
                if (GELU) v = 0.5f * v * (1.f + erff(v * 0.70710678118654752f));
                if (RES) v += res[(size_t)m * ldC + n];
                C[(size_t)m * ldC + n] = v;
            }
        }
    }
}

// ---------------- im2col for 16x16 stride-16 patch embed ----------------
__global__ __launch_bounds__(256) void im2col_kernel(const float* __restrict__ x,
                                                     float* __restrict__ out) {
    int idx = blockIdx.x * 256 + threadIdx.x;
    if (idx >= NTOK * CDIM) return;
    int n = idx / CDIM, k = idx % CDIM;
    int gy = n >> 5, gx = n & 31;
    int ph = k / 48;
    int r = k % 48;
    int pw = r / 3, ic = r % 3;
    out[idx] = x[ic * 512 * 512 + (gy * 16 + ph) * 512 + (gx * 16 + pw)];
}

// ---------------- warp-per-row LayerNorm ----------------
__global__ __launch_bounds__(256) void ln_warp(const float* __restrict__ in,
                                               const float* __restrict__ w,
                                               const float* __restrict__ b,
                                               float* __restrict__ out,
                                               int C, float eps) {
    int wid = threadIdx.x >> 5, lane = threadIdx.x & 31;
    int row = blockIdx.x * 8 + wid;
    const float* p = in + (size_t)row * C;
    float s = 0.f, ss = 0.f;
    for (int c = lane; c < C; c += 32) {
        float v = p[c];
        s += v;
        ss += v * v;
    }
    #pragma unroll
    for (int o = 16; o > 0; o >>= 1) {
        s += __shfl_xor_sync(0xffffffffu, s, o);
        ss += __shfl_xor_sync(0xffffffffu, ss, o);
    }
    float mean = s / C;
    float var = ss / C - mean * mean;
    float inv = rsqrtf(var + eps);
    float* q = out + (size_t)row * C;
    for (int c = lane; c < C; c += 32) q[c] = (p[c] - mean) * inv * w[c] + b[c];
}

// ---------------- softmax + rel-pos: global (row = 1024 keys) ----------------
__global__ __launch_bounds__(256) void softmax_glob(float* __restrict__ S,
                                                    const float* __restrict__ qkv,
                                                    const float* __restrict__ rel_h,
                                                    const float* __restrict__ rel_w) {
    int b = blockIdx.x;
    int h = b >> 10, q = b & 1023;
    int qy = q >> 5, qx = q & 31;
    int t = threadIdx.x, lane = t & 31, wid = t >> 5;
    __shared__ float qs[64], ph[32], pw[32], wred[8];
    float* Srow = S + ((size_t)h * 1024 + q) * 1024;
    if (t < 64) qs[t] = qkv[(size_t)q * 2304 + h * 64 + t];
    __syncthreads();
    if (t < 32) {
        const float* r = rel_h + (qy - t + 31) * 64;
        float s = 0.f;
        #pragma unroll
        for (int d = 0; d < 64; d++) s += qs[d] * r[d];
        ph[t] = s;
    } else if (t < 64) {
        int kx = t - 32;
        const float* r = rel_w + (qx - kx + 31) * 64;
        float s = 0.f;
        #pragma unroll
        for (int d = 0; d < 64; d++) s += qs[d] * r[d];
        pw[kx] = s;
    }
    __syncthreads();
    float vals[4];
    float lmax = -1e30f;
    #pragma unroll
    for (int i = 0; i < 4; i++) {
        int k = t + i * 256;
        float s = Srow[k] * ATT_SCALE + ph[k >> 5] + pw[k & 31];
        vals[i] = s;
        lmax = fmaxf(lmax, s);
    }
    #pragma unroll
    for (int o = 16; o > 0; o >>= 1) lmax = fmaxf(lmax, __shfl_xor_sync(0xffffffffu, lmax, o));
    if (lane == 0) wred[wid] = lmax;
    __syncthreads();
    float m = wred[0];
    #pragma unroll
    for (int j = 1; j < 8; j++) m = fmaxf(m, wred[j]);
    float lsum = 0.f;
    #pragma unroll
    for (int i = 0; i < 4; i++) {
        vals[i] = __expf(vals[i] - m);
        lsum += vals[i];
    }
    #pragma unroll
    for (int o = 16; o > 0; o >>= 1) lsum += __shfl_xor_sync(0xffffffffu, lsum, o);
    __syncthreads();
    if (lane == 0) wred[wid] = lsum;
    __syncthreads();
    float tot = 0.f;
    #pragma unroll
    for (int j = 0; j < 8; j++) tot += wred[j];
    float inv = 1.f / tot;
    #pragma unroll
    for (int i = 0; i < 4; i++) Srow[t + i * 256] = vals[i] * inv;
}

// ---------------- softmax + rel-pos: window (256 padded keys, 196 real) ----------------
__global__ __launch_bounds__(256) void softmax_win(float* __restrict__ S,
                                                   const float* __restrict__ Q,
                                                   const float* __restrict__ rel_h,
                                                   const float* __restrict__ rel_w) {
    int b = blockIdx.x;
    int bh = b >> 8, r = b & 255;
    int t = threadIdx.x, lane = t & 31, wid = t >> 5;
    float* Srow = S + ((size_t)bh * 256 + r) * 256;
    if (r >= 196) {
        Srow[t] = 0.f;
        return;
    }
    int iy = r / 14, ix = r % 14;
    __shared__ float qs[64], ph[14], pw[14], wred[8];
    if (t < 64) qs[t] = Q[((size_t)bh * 256 + r) * 64 + t];
    __syncthreads();
    if (t < 14) {
        const float* rp = rel_h + (iy - t + 13) * 64;
        float s = 0.f;
        #pragma unroll
        for (int d = 0; d < 64; d++) s += qs[d] * rp[d];
        ph[t] = s;
    } else if (t < 28) {
        int kx = t - 14;
        const float* rp = rel_w + (ix - kx + 13) * 64;
        float s = 0.f;
        #pragma unroll
        for (int d = 0; d < 64; d++) s += qs[d] * rp[d];
        pw[kx] = s;
    }
    __syncthreads();
    float s = -1e30f;
    if (t < 196) s = Srow[t] * ATT_SCALE + ph[t / 14] + pw[t % 14];
    float lmax = s;
    #pragma unroll
    for (int o = 16; o > 0; o >>= 1) lmax = fmaxf(lmax, __shfl_xor_sync(0xffffffffu, lmax, o));
    if (lane == 0) wred[wid] = lmax;
    __syncthreads();
    float m = wred[0];
    #pragma unroll
    for (int j = 1; j < 8; j++) m = fmaxf(m, wred[j]);
    float e = (t < 196) ? __expf(s - m) : 0.f;
    float lsum = e;
    #pragma unroll
    for (int o = 16; o > 0; o >>= 1) lsum += __shfl_xor_sync(0xffffffffu, lsum, o);
    __syncthreads();
    if (lane == 0) wred[wid] = lsum;
    __syncthreads();
    float tot = 0.f;
    #pragma unroll
    for (int j = 0; j < 8; j++) tot += wred[j];
    Srow[t] = e / tot;
}

// ---------------- qkv repack: window (pad each 14x14=196 window to 256 rows) ----------------
// Q/Kw/V all [win*12+head][256][64] token-major (K transposed via TRB in GEMM)
__global__ __launch_bounds__(256) void repack_win(const float* __restrict__ qkv,
                                                  float* __restrict__ Q,
                                                  float* __restrict__ Kw,
                                                  float* __restrict__ V) {
    int idx = blockIdx.x * 256 + threadIdx.x;  // 108*256*64
    int bh = idx >> 14;
    int r = (idx >> 6) & 255;
    int d = idx & 63;
    int w = bh / 12, h = bh % 12;
    int wy = w / 3, wx = w % 3;
    float q = 0.f, k = 0.f, v = 0.f;
    if (r < 196) {
        int iy = r / 14, ix = r % 14;
        int y = wy * 14 + iy, x = wx * 14 + ix;
        if (y < 32 && x < 32) {
            size_t base = (size_t)(y * 32 + x) * 2304 + h * 64 + d;
            q = qkv[base];
            k = qkv[base + 768];
            v = qkv[base + 1536];
        }
    }
    Q[idx] = q;
    Kw[idx] = k;
    V[idx] = v;
}

__global__ __launch_bounds__(256) void repack_back_win(const float* __restrict__ O,
                                                       float* __restrict__ out) {
    int idx = blockIdx.x * 256 + threadIdx.x;  // 1024*768
    int n = idx / 768, c = idx % 768;
    int h = c >> 6, d = c & 63;
    int y = n >> 5, x = n & 31;
    int w = (y / 14) * 3 + (x / 14);
    int r = (y % 14) * 14 + (x % 14);
    out[idx] = O[(((size_t)(w * 12 + h)) * 256 + r) * 64 + d];
}

// ---------------- 3x3 conv, 256->256, SAME, 32x32 spatial ----------------
__global__ __launch_bounds__(256) void conv3_kernel(const float* __restrict__ in,
                                                    const float* __restrict__ w,
                                                    float* __restrict__ out) {
    int n = blockIdx.x;
    int y = n / 32, x = n % 32;
    int co = threadIdx.x;
    __shared__ float s_in[9 * 256];
    #pragma unroll
    for (int p = 0; p < 9; p++) {
        int dy = p / 3 - 1, dx = p % 3 - 1;
        int yy = y + dy, xx = x + dx;
        s_in[p * 256 + co] =
            (yy >= 0 && yy < 32 && xx >= 0 && xx < 32) ? in[(size_t)(yy * 32 + xx) * 256 + co] : 0.f;
    }
    __syncthreads();
    float acc = 0.f;
    for (int p = 0; p < 9; p++) {
        const float* wp = w + (size_t)p * 256 * 256 + co;
        const float* ip = s_in + p * 256;
        #pragma unroll 8
        for (int ci = 0; ci < 256; ci++) acc += ip[ci] * wp[(size_t)ci * 256];
    }
    out[(size_t)n * 256 + co] = acc;
}

// ---------------- NHWC(1024,256) -> NCHW(256,1024) ----------------
__global__ __launch_bounds__(256) void transpose_out_kernel(const float* __restrict__ in,
                                                            float* __restrict__ out) {
    int idx = blockIdx.x * 256 + threadIdx.x;
    if (idx >= 256 * 1024) return;
    int c = idx / 1024;
    int n = idx % 1024;
    out[idx] = in[(size_t)n * 256 + c];
}

// ---------------- orchestration ----------------
extern "C" void kernel_launch(void* const* d_in, const int* in_sizes, int n_in,
                              void* d_out, int out_size) {
    const float* x          = (const float*)d_in[0];
    const float* patch_w    = (const float*)d_in[1];
    const float* patch_b    = (const float*)d_in[2];
    const float* pos_embed  = (const float*)d_in[3];
    const float* ln1_w      = (const float*)d_in[4];
    const float* ln1_b      = (const float*)d_in[5];
    const float* qkv_w      = (const float*)d_in[6];
    const float* qkv_b      = (const float*)d_in[7];
    const float* proj_w     = (const float*)d_in[8];
    const float* proj_b     = (const float*)d_in[9];
    const float* ln2_w      = (const float*)d_in[10];
    const float* ln2_b      = (const float*)d_in[11];
    const float* fc1_w      = (const float*)d_in[12];
    const float* fc1_b      = (const float*)d_in[13];
    const float* fc2_w      = (const float*)d_in[14];
    const float* fc2_b      = (const float*)d_in[15];
    const float* rel_h_win  = (const float*)d_in[16];
    const float* rel_w_win  = (const float*)d_in[17];
    const float* rel_h_glob = (const float*)d_in[18];
    const float* rel_w_glob = (const float*)d_in[19];
    const float* neck_w1    = (const float*)d_in[20];
    const float* neck_ln1_w = (const float*)d_in[21];
    const float* neck_ln1_b = (const float*)d_in[22];
    const float* neck_w2    = (const float*)d_in[23];
    const float* neck_ln2_w = (const float*)d_in[24];
    const float* neck_ln2_b = (const float*)d_in[25];

    float *h, *t, *qkv, *mid, *Q, *Kt, *V, *O, *S;
    cudaGetSymbolAddress((void**)&h, g_h);
    cudaGetSymbolAddress((void**)&t, g_t);
    cudaGetSymbolAddress((void**)&qkv, g_qkv);
    cudaGetSymbolAddress((void**)&mid, g_mid);
    cudaGetSymbolAddress((void**)&Q, g_Q);
    cudaGetSymbolAddress((void**)&Kt, g_Kt);
    cudaGetSymbolAddress((void**)&V, g_V);
    cudaGetSymbolAddress((void**)&O, g_O);
    cudaGetSymbolAddress((void**)&S, g_S);

    // patch embed: im2col + GEMM(+bias) + pos_embed residual
    im2col_kernel<<<(NTOK * CDIM + 255) / 256, 256>>>(x, t);
    gemm_tc<64, false, false, true><<<dim3(12, 8, 1), 128>>>(
        t, patch_w, patch_b, pos_embed, h, 1024, 768, 768, 768, 768, 768, 0, 0, 0);

    int wi = 0, gi = 0;
    for (int i = 0; i < 12; i++) {
        bool is_glob = (i == 2 || i == 5 || i == 8 || i == 11);
        ln_warp<<<128, 256>>>(h, ln1_w + i * 768, ln1_b + i * 768, t, 768, 1e-5f);
        gemm_tc<128, false, false, false><<<dim3(18, 8, 1), 128>>>(
            t, qkv_w + (size_t)i * 768 * 2304, qkv_b + (size_t)i * 2304, nullptr, qkv,
            1024, 2304, 768, 768, 2304, 2304, 0, 0, 0);
        if (is_glob) {
            // S[h] = Q (from qkv, ldA=2304) @ K^T (TRB from qkv, ldB=2304)
            gemm_tc<128, true, false, false><<<dim3(8, 8, 12), 128>>>(
                qkv, qkv + 768, nullptr, nullptr, S,
                1024, 1024, 64, 2304, 2304, 1024, 64, 64, 1L << 20);
            softmax_glob<<<12 * 1024, 256>>>(
                S, qkv, rel_h_glob + (size_t)gi * 63 * 64, rel_w_glob + (size_t)gi * 63 * 64);
            // t[:, h*64:(h+1)*64] = P[h] @ V[h]  (direct strided output)
            gemm_tc<64, false, false, false><<<dim3(1, 8, 12), 128>>>(
                S, qkv + 1536, nullptr, nullptr, t,
                1024, 64, 1024, 1024, 2304, 768, 1L << 20, 64, 64);
            gi++;
        } else {
            repack_win<<<108 * 256 * 64 / 256, 256>>>(qkv, Q, Kt, V);
            gemm_tc<128, true, false, false><<<dim3(2, 2, 108), 128>>>(
                Q, Kt, nullptr, nullptr, S,
                256, 256, 64, 64, 64, 256, 16384, 16384, 65536);
            softmax_win<<<108 * 256, 256>>>(
                S, Q, rel_h_win + (size_t)wi * 27 * 64, rel_w_win + (size_t)wi * 27 * 64);
            gemm_tc<64, false, false, false><<<dim3(1, 2, 108), 128>>>(
                S, V, nullptr, nullptr, O,
                256, 64, 256, 256, 64, 64, 65536, 16384, 16384);
            repack_back_win<<<NTOK * 768 / 256, 256>>>(O, t);
            wi++;
        }
        gemm_tc<64, false, false, true><<<dim3(12, 8, 1), 128>>>(
            t, proj_w + (size_t)i * 768 * 768, proj_b + (size_t)i * 768, h, h,
            1024, 768, 768, 768, 768, 768, 0, 0, 0);
        ln_warp<<<128, 256>>>(h, ln2_w + i * 768, ln2_b + i * 768, t, 768, 1e-5f);
        gemm_tc<128, false, true, false><<<dim3(24, 8, 1), 128>>>(
            t, fc1_w + (size_t)i * 768 * 3072, fc1_b + (size_t)i * 3072, nullptr, mid,
            1024, 3072, 768, 768, 3072, 3072, 0, 0, 0);
        gemm_tc<64, false, false, true><<<dim3(12, 8, 1), 128>>>(
            mid, fc2_w + (size_t)i * 3072 * 768, fc2_b + (size_t)i * 768, h, h,
            1024, 768, 3072, 3072, 768, 768, 0, 0, 0);
    }

    // neck
    gemm_tc<64, false, false, false><<<dim3(4, 8, 1), 128>>>(
        h, neck_w1, nullptr, nullptr, t, 1024, 256, 768, 768, 256, 256, 0, 0, 0);
    ln_warp<<<128, 256>>>(t, neck_ln1_w, neck_ln1_b, t, 256, 1e-6f);
    conv3_kernel<<<1024, 256>>>(t, neck_w2, mid);
    ln_warp<<<128, 256>>>(mid, neck_ln2_w, neck_ln2_b, mid, 256, 1e-6f);
    transpose_out_kernel<<<(256 * 1024 + 255) / 256, 256>>>(mid, (float*)d_out);
}

// round 12
// speedup vs baseline: 4.1615x; 1.1192x over previous
#include <cuda_runtime.h>
#include <math.h>
#include <stdint.h>

#define NTOK 1024
#define CDIM 768
#define ATT_SCALE 0.125f

// ---------------- scratch (device globals; no allocation allowed) ----------------
__device__ float g_h[NTOK * CDIM];
__device__ float g_t[NTOK * CDIM];
__device__ float g_qkv[NTOK * 3 * CDIM];
__device__ float g_mid[NTOK * 4 * CDIM];
#define ATT_BUF 1769472
__device__ float g_Q[ATT_BUF];
__device__ float g_Kt[ATT_BUF];   // window K, token-major
__device__ float g_V[ATT_BUF];
__device__ float g_O[ATT_BUF];
__device__ float g_S[12 * 1024 * 1024];

// ---------------- tf32 helper ----------------
__device__ __forceinline__ uint32_t f2tf(float f) {
    uint32_t u;
    asm("cvt.rna.tf32.f32 %0, %1;" : "=r"(u) : "f"(f));
    return u;
}

// ---------------- tf32 tensor-core GEMM, 8 warps, reg-prefetch pipeline ----------------
// C = [res +] act(A @ B + bias).  A: MxK row-major (ldA).
// B: if !TRB, KxN row-major (ldB); if TRB, B is NxK row-major (ldB) => A @ B^T.
// M%BM==0, N%BN==0, K%16==0.  Warp grid 2(m) x 4(n); warp tile (BM/2)x(BN/4).
template <int BM, int BN, bool TRB, bool GELU, bool RES>
__global__ __launch_bounds__(256, 2) void gemm_tc(const float* __restrict__ A,
                                                  const float* __restrict__ B,
                                                  const float* __restrict__ bias,
                                                  const float* __restrict__ res,
                                                  float* __restrict__ C,
                                                  int M, int N, int K,
                                                  int ldA, int ldB, int ldC,
                                                  long sA, long sB, long sC) {
    constexpr int MF = BM / 32;         // 16-row m-frags per warp
    constexpr int NF = BN / 32;         // 8-col n-frags per warp
    constexpr int AJ = BM * 16 / 1024;  // float4 loads per thread for A tile
    constexpr int BJ = BN * 16 / 1024;  // float4 loads per thread for B tile

    A += (long)blockIdx.z * sA;
    B += (long)blockIdx.z * sB;
    C += (long)blockIdx.z * sC;
    if (RES) res += (long)blockIdx.z * sC;

    __shared__ uint32_t As[16][BM + 4];
    __shared__ uint32_t Bs[16][BN + 4];

    int bm = blockIdx.y * BM, bn = blockIdx.x * BN;
    int tid = threadIdx.x;
    int lane = tid & 31, w = tid >> 5;
    int wm = (w & 1) * (BM / 2), wn = (w >> 1) * (BN / 4);
    int g = lane >> 2, tig = lane & 3;

    float acc[MF][NF][4];
    #pragma unroll
    for (int i = 0; i < MF; i++)
        #pragma unroll
        for (int j = 0; j < NF; j++)
            #pragma unroll
            for (int l = 0; l < 4; l++) acc[i][j][l] = 0.f;

    float4 pa[AJ], pb[BJ];

    // prefetch first k-slab
    #pragma unroll
    for (int j = 0; j < AJ; j++) {
        int it = tid + j * 256;
        int r = it >> 2, c4 = (it & 3) * 4;
        pa[j] = *(const float4*)(A + (size_t)(bm + r) * ldA + c4);
    }
    if (TRB) {
        #pragma unroll
        for (int j = 0; j < BJ; j++) {
            int it = tid + j * 256;
            int r = it >> 2, c4 = (it & 3) * 4;
            pb[j] = *(const float4*)(B + (size_t)(bn + r) * ldB + c4);
        }
    } else {
        constexpr int FPR = BN / 4;
        #pragma unroll
        for (int j = 0; j < BJ; j++) {
            int it = tid + j * 256;
            int r = it / FPR, c4 = (it % FPR) * 4;
            pb[j] = *(const float4*)(B + (size_t)r * ldB + bn + c4);
        }
    }

    for (int k0 = 0; k0 < K; k0 += 16) {
        // store prefetched slab to smem (tf32-converted)
        #pragma unroll
        for (int j = 0; j < AJ; j++) {
            int it = tid + j * 256;
            int r = it >> 2, c4 = (it & 3) * 4;
            As[c4 + 0][r] = f2tf(pa[j].x);
            As[c4 + 1][r] = f2tf(pa[j].y);
            As[c4 + 2][r] = f2tf(pa[j].z);
            As[c4 + 3][r] = f2tf(pa[j].w);
        }
        if (TRB) {
            #pragma unroll
            for (int j = 0; j < BJ; j++) {
                int it = tid + j * 256;
                int r = it >> 2, c4 = (it & 3) * 4;
                Bs[c4 + 0][r] = f2tf(pb[j].x);
                Bs[c4 + 1][r] = f2tf(pb[j].y);
                Bs[c4 + 2][r] = f2tf(pb[j].z);
                Bs[c4 + 3][r] = f2tf(pb[j].w);
            }
        } else {
            constexpr int FPR = BN / 4;
            #pragma unroll
            for (int j = 0; j < BJ; j++) {
                int it = tid + j * 256;
                int rr = it / FPR, c4 = (it % FPR) * 4;
                Bs[rr][c4 + 0] = f2tf(pb[j].x);
                Bs[rr][c4 + 1] = f2tf(pb[j].y);
                Bs[rr][c4 + 2] = f2tf(pb[j].z);
                Bs[rr][c4 + 3] = f2tf(pb[j].w);
            }
        }
        __syncthreads();

        // prefetch next slab while computing this one
        int kn = k0 + 16;
        if (kn < K) {
            #pragma unroll
            for (int j = 0; j < AJ; j++) {
                int it = tid + j * 256;
                int r = it >> 2, c4 = (it & 3) * 4;
                pa[j] = *(const float4*)(A + (size_t)(bm + r) * ldA + kn + c4);
            }
            if (TRB) {
                #pragma unroll
                for (int j = 0; j < BJ; j++) {
                    int it = tid + j * 256;
                    int r = it >> 2, c4 = (it & 3) * 4;
                    pb[j] = *(const float4*)(B + (size_t)(bn + r) * ldB + kn + c4);
                }
            } else {
                constexpr int FPR = BN / 4;
                #pragma unroll
                for (int j = 0; j < BJ; j++) {
                    int it = tid + j * 256;
                    int r = it / FPR, c4 = (it % FPR) * 4;
                    pb[j] = *(const float4*)(B + (size_t)(kn + r) * ldB + bn + c4);
                }
            }
        }

        #pragma unroll
        for (int ks = 0; ks < 16; ks += 8) {
            uint32_t af[MF][4], bf[NF][2];
            #pragma unroll
            for (int mf = 0; mf < MF; mf++) {
                int mbase = wm + mf * 16 + g;
                af[mf][0] = As[ks + tig][mbase];
                af[mf][1] = As[ks + tig][mbase + 8];
                af[mf][2] = As[ks + tig + 4][mbase];
                af[mf][3] = As[ks + tig + 4][mbase + 8];
            }
            #pragma unroll
            for (int nf = 0; nf < NF; nf++) {
                int nbase = wn + nf * 8 + g;
                bf[nf][0] = Bs[ks + tig][nbase];
                bf[nf][1] = Bs[ks + tig + 4][nbase];
            }
            #pragma unroll
            for (int mf = 0; mf < MF; mf++)
                #pragma unroll
                for (int nf = 0; nf < NF; nf++) {
                    asm volatile(
                        "mma.sync.aligned.m16n8k8.row.col.f32.tf32.tf32.f32 "
                        "{%0,%1,%2,%3}, {%4,%5,%6,%7}, {%8,%9}, {%0,%1,%2,%3};"
                        : "+f"(acc[mf][nf][0]), "+f"(acc[mf][nf][1]),
                          "+f"(acc[mf][nf][2]), "+f"(acc[mf][nf][3])
                        : "r"(af[mf][0]), "r"(af[mf][1]), "r"(af[mf][2]), "r"(af[mf][3]),
                          "r"(bf[nf][0]), "r"(bf[nf][1]));
                }
        }
        __syncthreads();
    }
    // epilogue
    #pragma unroll
    for (int mf = 0; mf < MF; mf++) {
        #pragma unroll
        for (int nf = 0; nf < NF; nf++) {
            int row0 = bm + wm + mf * 16 + g;
            int col0 = bn + wn + nf * 8 + tig * 2;
            #pragma unroll
            for (int e = 0; e < 4; e++) {
                int m = row0 + (e >> 1) * 8;
                int n = col0 + (e & 1);
                float v = acc[mf][nf][e];
                if (bias) v += bias[n];
                if (GELU) v = 0.5f * v * (1.f + erff(v * 0.70710678118654752f));
                if (RES) v += res[(size_t)m * ldC + n];
                C[(size_t)m * ldC + n] = v;
            }
        }
    }
}

// ---------------- im2col for 16x16 stride-16 patch embed ----------------
__global__ __launch_bounds__(256) void im2col_kernel(const float* __restrict__ x,
                                                     float* __restrict__ out) {
    int idx = blockIdx.x * 256 + threadIdx.x;
    if (idx >= NTOK * CDIM) return;
    int n = idx / CDIM, k = idx % CDIM;
    int gy = n >> 5, gx = n & 31;
    int ph = k / 48;
    int r = k % 48;
    int pw = r / 3, ic = r % 3;
    out[idx] = x[ic * 512 * 512 + (gy * 16 + ph) * 512 + (gx * 16 + pw)];
}

// ---------------- warp-per-row LayerNorm ----------------
__global__ __launch_bounds__(256) void ln_warp(const float* __restrict__ in,
                                               const float* __restrict__ w,
                                               const float* __restrict__ b,
                                               float* __restrict__ out,
                                               int C, float eps) {
    int wid = threadIdx.x >> 5, lane = threadIdx.x & 31;
    int row = blockIdx.x * 8 + wid;
    const float* p = in + (size_t)row * C;
    float s = 0.f, ss = 0.f;
    for (int c = lane; c < C; c += 32) {
        float v = p[c];
        s += v;
        ss += v * v;
    }
    #pragma unroll
    for (int o = 16; o > 0; o >>= 1) {
        s += __shfl_xor_sync(0xffffffffu, s, o);
        ss += __shfl_xor_sync(0xffffffffu, ss, o);
    }
    float mean = s / C;
    float var = ss / C - mean * mean;
    float inv = rsqrtf(var + eps);
    float* q = out + (size_t)row * C;
    for (int c = lane; c < C; c += 32) q[c] = (p[c] - mean) * inv * w[c] + b[c];
}

// ---------------- softmax + rel-pos: global (row = 1024 keys) ----------------
__global__ __launch_bounds__(256) void softmax_glob(float* __restrict__ S,
                                                    const float* __restrict__ qkv,
                                                    const float* __restrict__ rel_h,
                                                    const float* __restrict__ rel_w) {
    int b = blockIdx.x;
    int h = b >> 10, q = b & 1023;
    int qy = q >> 5, qx = q & 31;
    int t = threadIdx.x, lane = t & 31, wid = t >> 5;
    __shared__ float qs[64], ph[32], pw[32], wred[8];
    float* Srow = S + ((size_t)h * 1024 + q) * 1024;
    if (t < 64) qs[t] = qkv[(size_t)q * 2304 + h * 64 + t];
    __syncthreads();
    if (t < 32) {
        const float* r = rel_h + (qy - t + 31) * 64;
        float s = 0.f;
        #pragma unroll
        for (int d = 0; d < 64; d++) s += qs[d] * r[d];
        ph[t] = s;
    } else if (t < 64) {
        int kx = t - 32;
        const float* r = rel_w + (qx - kx + 31) * 64;
        float s = 0.f;
        #pragma unroll
        for (int d = 0; d < 64; d++) s += qs[d] * r[d];
        pw[kx] = s;
    }
    __syncthreads();
    float vals[4];
    float lmax = -1e30f;
    #pragma unroll
    for (int i = 0; i < 4; i++) {
        int k = t + i * 256;
        float s = Srow[k] * ATT_SCALE + ph[k >> 5] + pw[k & 31];
        vals[i] = s;
        lmax = fmaxf(lmax, s);
    }
    #pragma unroll
    for (int o = 16; o > 0; o >>= 1) lmax = fmaxf(lmax, __shfl_xor_sync(0xffffffffu, lmax, o));
    if (lane == 0) wred[wid] = lmax;
    __syncthreads();
    float m = wred[0];
    #pragma unroll
    for (int j = 1; j < 8; j++) m = fmaxf(m, wred[j]);
    float lsum = 0.f;
    #pragma unroll
    for (int i = 0; i < 4; i++) {
        vals[i] = __expf(vals[i] - m);
        lsum += vals[i];
    }
    #pragma unroll
    for (int o = 16; o > 0; o >>= 1) lsum += __shfl_xor_sync(0xffffffffu, lsum, o);
    __syncthreads();
    if (lane == 0) wred[wid] = lsum;
    __syncthreads();
    float tot = 0.f;
    #pragma unroll
    for (int j = 0; j < 8; j++) tot += wred[j];
    float inv = 1.f / tot;
    #pragma unroll
    for (int i = 0; i < 4; i++) Srow[t + i * 256] = vals[i] * inv;
}

// ---------------- softmax + rel-pos: window (256 padded keys, 196 real) ----------------
__global__ __launch_bounds__(256) void softmax_win(float* __restrict__ S,
                                                   const float* __restrict__ Q,
                                                   const float* __restrict__ rel_h,
                                                   const float* __restrict__ rel_w) {
    int b = blockIdx.x;
    int bh = b >> 8, r = b & 255;
    int t = threadIdx.x, lane = t & 31, wid = t >> 5;
    float* Srow = S + ((size_t)bh * 256 + r) * 256;
    if (r >= 196) {
        Srow[t] = 0.f;
        return;
    }
    int iy = r / 14, ix = r % 14;
    __shared__ float qs[64], ph[14], pw[14], wred[8];
    if (t < 64) qs[t] = Q[((size_t)bh * 256 + r) * 64 + t];
    __syncthreads();
    if (t < 14) {
        const float* rp = rel_h + (iy - t + 13) * 64;
        float s = 0.f;
        #pragma unroll
        for (int d = 0; d < 64; d++) s += qs[d] * rp[d];
        ph[t] = s;
    } else if (t < 28) {
        int kx = t - 14;
        const float* rp = rel_w + (ix - kx + 13) * 64;
        float s = 0.f;
        #pragma unroll
        for (int d = 0; d < 64; d++) s += qs[d] * rp[d];
        pw[kx] = s;
    }
    __syncthreads();
    float s = -1e30f;
    if (t < 196) s = Srow[t] * ATT_SCALE + ph[t / 14] + pw[t % 14];
    float lmax = s;
    #pragma unroll
    for (int o = 16; o > 0; o >>= 1) lmax = fmaxf(lmax, __shfl_xor_sync(0xffffffffu, lmax, o));
    if (lane == 0) wred[wid] = lmax;
    __syncthreads();
    float m = wred[0];
    #pragma unroll
    for (int j = 1; j < 8; j++) m = fmaxf(m, wred[j]);
    float e = (t < 196) ? __expf(s - m) : 0.f;
    float lsum = e;
    #pragma unroll
    for (int o = 16; o > 0; o >>= 1) lsum += __shfl_xor_sync(0xffffffffu, lsum, o);
    __syncthreads();
    if (lane == 0) wred[wid] = lsum;
    __syncthreads();
    float tot = 0.f;
    #pragma unroll
    for (int j = 0; j < 8; j++) tot += wred[j];
    Srow[t] = e / tot;
}

// ---------------- qkv repack: window (pad each 14x14=196 window to 256 rows) ----------------
__global__ __launch_bounds__(256) void repack_win(const float* __restrict__ qkv,
                                                  float* __restrict__ Q,
                                                  float* __restrict__ Kw,
                                                  float* __restrict__ V) {
    int idx = blockIdx.x * 256 + threadIdx.x;  // 108*256*64
    int bh = idx >> 14;
    int r = (idx >> 6) & 255;
    int d = idx & 63;
    int w = bh / 12, h = bh % 12;
    int wy = w / 3, wx = w % 3;
    float q = 0.f, k = 0.f, v = 0.f;
    if (r < 196) {
        int iy = r / 14, ix = r % 14;
        int y = wy * 14 + iy, x = wx * 14 + ix;
        if (y < 32 && x < 32) {
            size_t base = (size_t)(y * 32 + x) * 2304 + h * 64 + d;
            q = qkv[base];
            k = qkv[base + 768];
            v = qkv[base + 1536];
        }
    }
    Q[idx] = q;
    Kw[idx] = k;
    V[idx] = v;
}

__global__ __launch_bounds__(256) void repack_back_win(const float* __restrict__ O,
                                                       float* __restrict__ out) {
    int idx = blockIdx.x * 256 + threadIdx.x;  // 1024*768
    int n = idx / 768, c = idx % 768;
    int h = c >> 6, d = c & 63;
    int y = n >> 5, x = n & 31;
    int w = (y / 14) * 3 + (x / 14);
    int r = (y % 14) * 14 + (x % 14);
    out[idx] = O[(((size_t)(w * 12 + h)) * 256 + r) * 64 + d];
}

// ---------------- 3x3 conv, 256->256, SAME, 32x32 spatial ----------------
__global__ __launch_bounds__(256) void conv3_kernel(const float* __restrict__ in,
                                                    const float* __restrict__ w,
                                                    float* __restrict__ out) {
    int n = blockIdx.x;
    int y = n / 32, x = n % 32;
    int co = threadIdx.x;
    __shared__ float s_in[9 * 256];
    #pragma unroll
    for (int p = 0; p < 9; p++) {
        int dy = p / 3 - 1, dx = p % 3 - 1;
        int yy = y + dy, xx = x + dx;
        s_in[p * 256 + co] =
            (yy >= 0 && yy < 32 && xx >= 0 && xx < 32) ? in[(size_t)(yy * 32 + xx) * 256 + co] : 0.f;
    }
    __syncthreads();
    float acc = 0.f;
    for (int p = 0; p < 9; p++) {
        const float* wp = w + (size_t)p * 256 * 256 + co;
        const float* ip = s_in + p * 256;
        #pragma unroll 8
        for (int ci = 0; ci < 256; ci++) acc += ip[ci] * wp[(size_t)ci * 256];
    }
    out[(size_t)n * 256 + co] = acc;
}

// ---------------- NHWC(1024,256) -> NCHW(256,1024) ----------------
__global__ __launch_bounds__(256) void transpose_out_kernel(const float* __restrict__ in,
                                                            float* __restrict__ out) {
    int idx = blockIdx.x * 256 + threadIdx.x;
    if (idx >= 256 * 1024) return;
    int c = idx / 1024;
    int n = idx % 1024;
    out[idx] = in[(size_t)n * 256 + c];
}

// ---------------- orchestration ----------------
extern "C" void kernel_launch(void* const* d_in, const int* in_sizes, int n_in,
                              void* d_out, int out_size) {
    const float* x          = (const float*)d_in[0];
    const float* patch_w    = (const float*)d_in[1];
    const float* patch_b    = (const float*)d_in[2];
    const float* pos_embed  = (const float*)d_in[3];
    const float* ln1_w      = (const float*)d_in[4];
    const float* ln1_b      = (const float*)d_in[5];
    const float* qkv_w      = (const float*)d_in[6];
    const float* qkv_b      = (const float*)d_in[7];
    const float* proj_w     = (const float*)d_in[8];
    const float* proj_b     = (const float*)d_in[9];
    const float* ln2_w      = (const float*)d_in[10];
    const float* ln2_b      = (const float*)d_in[11];
    const float* fc1_w      = (const float*)d_in[12];
    const float* fc1_b      = (const float*)d_in[13];
    const float* fc2_w      = (const float*)d_in[14];
    const float* fc2_b      = (const float*)d_in[15];
    const float* rel_h_win  = (const float*)d_in[16];
    const float* rel_w_win  = (const float*)d_in[17];
    const float* rel_h_glob = (const float*)d_in[18];
    const float* rel_w_glob = (const float*)d_in[19];
    const float* neck_w1    = (const float*)d_in[20];
    const float* neck_ln1_w = (const float*)d_in[21];
    const float* neck_ln1_b = (const float*)d_in[22];
    const float* neck_w2    = (const float*)d_in[23];
    const float* neck_ln2_w = (const float*)d_in[24];
    const float* neck_ln2_b = (const float*)d_in[25];

    float *h, *t, *qkv, *mid, *Q, *Kt, *V, *O, *S;
    cudaGetSymbolAddress((void**)&h, g_h);
    cudaGetSymbolAddress((void**)&t, g_t);
    cudaGetSymbolAddress((void**)&qkv, g_qkv);
    cudaGetSymbolAddress((void**)&mid, g_mid);
    cudaGetSymbolAddress((void**)&Q, g_Q);
    cudaGetSymbolAddress((void**)&Kt, g_Kt);
    cudaGetSymbolAddress((void**)&V, g_V);
    cudaGetSymbolAddress((void**)&O, g_O);
    cudaGetSymbolAddress((void**)&S, g_S);

    // patch embed: im2col + GEMM(+bias) + pos_embed residual
    im2col_kernel<<<(NTOK * CDIM + 255) / 256, 256>>>(x, t);
    gemm_tc<64, 64, false, false, true><<<dim3(12, 16, 1), 256>>>(
        t, patch_w, patch_b, pos_embed, h, 1024, 768, 768, 768, 768, 768, 0, 0, 0);

    int wi = 0, gi = 0;
    for (int i = 0; i < 12; i++) {
        bool is_glob = (i == 2 || i == 5 || i == 8 || i == 11);
        ln_warp<<<128, 256>>>(h, ln1_w + i * 768, ln1_b + i * 768, t, 768, 1e-5f);
        gemm_tc<128, 128, false, false, false><<<dim3(18, 8, 1), 256>>>(
            t, qkv_w + (size_t)i * 768 * 2304, qkv_b + (size_t)i * 2304, nullptr, qkv,
            1024, 2304, 768, 768, 2304, 2304, 0, 0, 0);
        if (is_glob) {
            // S[h] = Q (from qkv, ldA=2304) @ K^T (TRB from qkv, ldB=2304)
            gemm_tc<128, 128, true, false, false><<<dim3(8, 8, 12), 256>>>(
                qkv, qkv + 768, nullptr, nullptr, S,
                1024, 1024, 64, 2304, 2304, 1024, 64, 64, 1L << 20);
            softmax_glob<<<12 * 1024, 256>>>(
                S, qkv, rel_h_glob + (size_t)gi * 63 * 64, rel_w_glob + (size_t)gi * 63 * 64);
            // t[:, h*64:(h+1)*64] = P[h] @ V[h]  (direct strided output)
            gemm_tc<64, 64, false, false, false><<<dim3(1, 16, 12), 256>>>(
                S, qkv + 1536, nullptr, nullptr, t,
                1024, 64, 1024, 1024, 2304, 768, 1L << 20, 64, 64);
            gi++;
        } else {
            repack_win<<<108 * 256 * 64 / 256, 256>>>(qkv, Q, Kt, V);
            gemm_tc<128, 128, true, false, false><<<dim3(2, 2, 108), 256>>>(
                Q, Kt, nullptr, nullptr, S,
                256, 256, 64, 64, 64, 256, 16384, 16384, 65536);
            softmax_win<<<108 * 256, 256>>>(
                S, Q, rel_h_win + (size_t)wi * 27 * 64, rel_w_win + (size_t)wi * 27 * 64);
            gemm_tc<64, 64, false, false, false><<<dim3(1, 4, 108), 256>>>(
                S, V, nullptr, nullptr, O,
                256, 64, 256, 256, 64, 64, 65536, 16384, 16384);
            repack_back_win<<<NTOK * 768 / 256, 256>>>(O, t);
            wi++;
        }
        gemm_tc<64, 64, false, false, true><<<dim3(12, 16, 1), 256>>>(
            t, proj_w + (size_t)i * 768 * 768, proj_b + (size_t)i * 768, h, h,
            1024, 768, 768, 768, 768, 768, 0, 0, 0);
        ln_warp<<<128, 256>>>(h, ln2_w + i * 768, ln2_b + i * 768, t, 768, 1e-5f);
        gemm_tc<128, 128, false, true, false><<<dim3(24, 8, 1), 256>>>(
            t, fc1_w + (size_t)i * 768 * 3072, fc1_b + (size_t)i * 3072, nullptr, mid,
            1024, 3072, 768, 768, 3072, 3072, 0, 0, 0);
        gemm_tc<64, 64, false, false, true><<<dim3(12, 16, 1), 256>>>(
            mid, fc2_w + (size_t)i * 3072 * 768, fc2_b + (size_t)i * 768, h, h,
            1024, 768, 3072, 3072, 768, 768, 0, 0, 0);
    }

    // neck
    gemm_tc<64, 64, false, false, false><<<dim3(4, 16, 1), 256>>>(
        h, neck_w1, nullptr, nullptr, t, 1024, 256, 768, 768, 256, 256, 0, 0, 0);
    ln_warp<<<128, 256>>>(t, neck_ln1_w, neck_ln1_b, t, 256, 1e-6f);
    conv3_kernel<<<1024, 256>>>(t, neck_w2, mid);
    ln_warp<<<128, 256>>>(mid, neck_ln2_w, neck_ln2_b, mid, 256, 1e-6f);
    transpose_out_kernel<<<(256 * 1024 + 255) / 256, 256>>>(mid, (float*)d_out);
}